// round 12
// baseline (speedup 1.0000x reference)
#include <cuda_runtime.h>
#include <cuda_bf16.h>
#include <cstdint>
#include <cstddef>

#define HS 512
#define BS 16
#define SS 2048
#define LC 16              // chunk length (steps per chunk)
#define CC 128             // number of chunks
#define MR (CC*BS)         // 2048 rows per scan step
#define GM 32768           // big-GEMM M (BS*SS)

// ---------------- scratch (static __device__; no allocation anywhere) ----------------
static __device__ float g_bxc[(size_t)SS * BS * HS];   // [i<16][j<128][b<16][h]
static __device__ float g_hs [(size_t)BS * SS * HS];   // fallback hs storage
static __device__ float g_H0[MR * HS];                 // phase-1 finals (fp32)
static __device__ float g_Hi[MR * HS];                 // chunk initial states
static __device__ float g_P0[HS * HS];
static __device__ float g_P1[HS * HS];                 // A^16 lives here
static __device__ __nv_bfloat16 g_Ahi[(size_t)GM * HS];  // big-GEMM A operand hi
static __device__ __nv_bfloat16 g_Alo[(size_t)GM * HS];  // big-GEMM A operand lo
static __device__ __nv_bfloat16 g_Whi[HS * HS];          // weight operand hi (B then C)
static __device__ __nv_bfloat16 g_Wlo[HS * HS];
static __device__ __nv_bfloat16 g_Sah[HS * HS];          // scan A-weight bf16 hi
static __device__ __nv_bfloat16 g_Sal[HS * HS];          // scan A-weight bf16 lo
static __device__ unsigned g_cnt3;                     // cross-scan barrier
static __device__ unsigned g_cntS;                     // fused-squaring barrier

// ---------------- warp MMA + cp.async helpers ----------------
__device__ __forceinline__ uint32_t smem_u32(const void* p) {
    uint32_t a;
    asm("{ .reg .u64 t; cvta.to.shared.u64 t, %1; cvt.u32.u64 %0, t; }" : "=r"(a) : "l"(p));
    return a;
}
__device__ __forceinline__ void ldmx4(uint32_t* r, uint32_t addr)
{
    asm volatile("ldmatrix.sync.aligned.m8n8.x4.shared.b16 {%0,%1,%2,%3}, [%4];"
        : "=r"(r[0]), "=r"(r[1]), "=r"(r[2]), "=r"(r[3]) : "r"(addr));
}
__device__ __forceinline__ void mma16816(float* c, const uint32_t* a, const uint32_t* b)
{
    asm volatile(
        "mma.sync.aligned.m16n8k16.row.col.f32.bf16.bf16.f32 "
        "{%0,%1,%2,%3}, {%4,%5,%6,%7}, {%8,%9}, {%0,%1,%2,%3};"
        : "+f"(c[0]), "+f"(c[1]), "+f"(c[2]), "+f"(c[3])
        : "r"(a[0]), "r"(a[1]), "r"(a[2]), "r"(a[3]), "r"(b[0]), "r"(b[1]));
}
__device__ __forceinline__ void cp16(uint32_t d, const void* s)
{
    asm volatile("{ .reg .u64 g; cvta.to.global.u64 g, %1; "
                 "cp.async.cg.shared.global [%0], [g], 16; }"
                 :: "r"(d), "l"(s) : "memory");
}
#define CP_COMMIT() asm volatile("cp.async.commit_group;" ::: "memory")
#define CP_WAIT(n)  asm volatile("cp.async.wait_group %0;" :: "n"(n) : "memory")

// ---------------- fp32 -> bf16 hi/lo splits ----------------
__device__ __forceinline__ void split4(float4 v, uint2& h, uint2& l)
{
    __nv_bfloat162 h01 = __floats2bfloat162_rn(v.x, v.y);
    __nv_bfloat162 h23 = __floats2bfloat162_rn(v.z, v.w);
    float2 f01 = __bfloat1622float2(h01);
    float2 f23 = __bfloat1622float2(h23);
    __nv_bfloat162 l01 = __floats2bfloat162_rn(v.x - f01.x, v.y - f01.y);
    __nv_bfloat162 l23 = __floats2bfloat162_rn(v.z - f23.x, v.w - f23.y);
    h.x = *reinterpret_cast<uint32_t*>(&h01);
    h.y = *reinterpret_cast<uint32_t*>(&h23);
    l.x = *reinterpret_cast<uint32_t*>(&l01);
    l.y = *reinterpret_cast<uint32_t*>(&l23);
}
__device__ __forceinline__ void split2(float a, float b, uint32_t& h, uint32_t& l)
{
    __nv_bfloat162 hh = __floats2bfloat162_rn(a, b);
    float2 f = __bfloat1622float2(hh);
    __nv_bfloat162 ll = __floats2bfloat162_rn(a - f.x, b - f.y);
    h = *reinterpret_cast<uint32_t*>(&hh);
    l = *reinterpret_cast<uint32_t*>(&ll);
}

// ---------------- global barrier (co-resident grids only; sq/cross) ----------------
__device__ __forceinline__ void gbar(unsigned* cnt, unsigned target)
{
    __threadfence();
    __syncthreads();
    if (threadIdx.x == 0) {
        atomicAdd(cnt, 1u);
        while (*(volatile unsigned*)cnt < target) { __nanosleep(40); }
        __threadfence();
    }
    __syncthreads();
}

// ---------------- zero init ----------------
__global__ void k_zero()
{
    int i = blockIdx.x * blockDim.x + threadIdx.x;
    if (i < MR * HS) g_Hi[i] = 0.f;
    if (i == 0) { g_cnt3 = 0u; g_cntS = 0u; }
}

// ---------------- split kernels ----------------
__global__ __launch_bounds__(128) void k_split_x(const float* __restrict__ x)
{
    int r  = blockIdx.x;                // gemm row = i*2048 + j*16 + b
    int ii = r >> 11;
    int jb = r & 2047;
    int srow = (jb & 15) * SS + ((jb >> 4) << 4) + ii;
    int c = threadIdx.x << 2;
    float4 v = *(const float4*)&x[(size_t)srow * HS + c];
    uint2 h, l;
    split4(v, h, l);
    *(uint2*)&g_Ahi[(size_t)r * HS + c] = h;
    *(uint2*)&g_Alo[(size_t)r * HS + c] = l;
}

__global__ __launch_bounds__(128) void k_split_w(const float* __restrict__ W)
{
    int r = blockIdx.x;
    int c = threadIdx.x << 2;
    float4 v = *(const float4*)&W[(size_t)r * HS + c];
    uint2 h, l;
    split4(v, h, l);
    *(uint2*)&g_Whi[(size_t)r * HS + c] = h;
    *(uint2*)&g_Wlo[(size_t)r * HS + c] = l;
}

__global__ __launch_bounds__(128) void k_split_A(const float* __restrict__ W)
{
    int r = blockIdx.x;
    int c = threadIdx.x << 2;
    float4 v = *(const float4*)&W[(size_t)r * HS + c];
    uint2 h, l;
    split4(v, h, l);
    *(uint2*)&g_Sah[(size_t)r * HS + c] = h;
    *(uint2*)&g_Sal[(size_t)r * HS + c] = l;
}

// ---------------- bf16x3 big GEMM via mma.sync (proven 220us config) ----------------
#define GEMM_SMEM (4 * 128 * 72 * 2)     // 73728 bytes

__global__ __launch_bounds__(256) void k_gemm_mma(float* __restrict__ Out, int mode)
{
    if (mode == 1) Out = g_bxc;
    extern __shared__ __nv_bfloat16 sb[];
    __nv_bfloat16* sAh = sb;
    __nv_bfloat16* sAl = sb + 9216;
    __nv_bfloat16* sWh = sb + 18432;
    __nv_bfloat16* sWl = sb + 27648;

    const int tid  = threadIdx.x;
    const int lane = tid & 31;
    const int wid  = tid >> 5;
    const int row0 = blockIdx.y << 7;
    const int col0 = blockIdx.x << 7;
    const int wm   = wid >> 2;
    const int wn   = wid & 3;

    const int lrow = tid >> 1;
    const int lseg = (tid & 1) << 5;

    float acc[4][4][4];
#pragma unroll
    for (int mt = 0; mt < 4; ++mt)
#pragma unroll
        for (int nt = 0; nt < 4; ++nt)
#pragma unroll
            for (int q = 0; q < 4; ++q) acc[mt][nt][q] = 0.f;

    const uint32_t sAh32 = smem_u32(sAh);
    const uint32_t sAl32 = smem_u32(sAl);
    const uint32_t sWh32 = smem_u32(sWh);
    const uint32_t sWl32 = smem_u32(sWl);

    const uint32_t a_lrow = (uint32_t)(wm * 64 + (lane & 15));
    const uint32_t b_lrow = (uint32_t)(wn * 32 + (lane & 15));
    const uint32_t khalf  = (uint32_t)((lane >> 4) << 3);

    for (int kc = 0; kc < 8; ++kc) {
        __syncthreads();
        {
            const size_t gA = (size_t)(row0 + lrow) * HS + kc * 64 + lseg;
            const size_t gW = (size_t)(col0 + lrow) * HS + kc * 64 + lseg;
            const uint32_t so = (uint32_t)(lrow * 72 + lseg);
#pragma unroll
            for (int i = 0; i < 4; ++i) {
                *(uint4*)(sAh + so + i*8) = *(const uint4*)(g_Ahi + gA + i*8);
                *(uint4*)(sAl + so + i*8) = *(const uint4*)(g_Alo + gA + i*8);
                *(uint4*)(sWh + so + i*8) = *(const uint4*)(g_Whi + gW + i*8);
                *(uint4*)(sWl + so + i*8) = *(const uint4*)(g_Wlo + gW + i*8);
            }
        }
        __syncthreads();

#pragma unroll
        for (int ks = 0; ks < 4; ++ks) {
            const uint32_t kcol = (uint32_t)(ks * 16) + khalf;
            uint32_t ah[4][4], al[4][4], bh[4][2], bl[4][2];
#pragma unroll
            for (int mt = 0; mt < 4; ++mt) {
                uint32_t off = ((a_lrow + mt*16) * 72 + kcol) * 2;
                ldmx4(ah[mt], sAh32 + off);
                ldmx4(al[mt], sAl32 + off);
            }
#pragma unroll
            for (int bt = 0; bt < 2; ++bt) {
                uint32_t off = ((b_lrow + bt*16) * 72 + kcol) * 2;
                uint32_t qh[4], ql[4];
                ldmx4(qh, sWh32 + off);
                ldmx4(ql, sWl32 + off);
                bh[2*bt+0][0] = qh[0]; bh[2*bt+0][1] = qh[2];
                bh[2*bt+1][0] = qh[1]; bh[2*bt+1][1] = qh[3];
                bl[2*bt+0][0] = ql[0]; bl[2*bt+0][1] = ql[2];
                bl[2*bt+1][0] = ql[1]; bl[2*bt+1][1] = ql[3];
            }
#pragma unroll
            for (int mt = 0; mt < 4; ++mt)
#pragma unroll
                for (int nt = 0; nt < 4; ++nt) {
                    mma16816(acc[mt][nt], ah[mt], bh[nt]);
                    mma16816(acc[mt][nt], ah[mt], bl[nt]);
                    mma16816(acc[mt][nt], al[mt], bh[nt]);
                }
        }
    }

    const int r_base = row0 + wm * 64 + (lane >> 2);
    const int c_base = col0 + wn * 32 + ((lane & 3) << 1);
#pragma unroll
    for (int mt = 0; mt < 4; ++mt)
#pragma unroll
        for (int nt = 0; nt < 4; ++nt) {
            size_t o0 = (size_t)(r_base + mt*16)     * HS + c_base + nt*8;
            size_t o1 = (size_t)(r_base + mt*16 + 8) * HS + c_base + nt*8;
            *(float2*)&Out[o0] = make_float2(acc[mt][nt][0], acc[mt][nt][1]);
            *(float2*)&Out[o1] = make_float2(acc[mt][nt][2], acc[mt][nt][3]);
        }
}

// ---------------- CTA-local tensor-core scan ----------------
// One CTA per chunk j (128 CTAs). H[16][512] bf16 pair resident in smem across
// all LC steps; A streams from L2 (bf16 hi/lo) via double-buffered cp.async.
// smem (halves): Hh [16][520] @0, Hl @8320, A stage @16640: buf b @ +b*36864:
//   hi rows 256x72 @ +0, lo @ +18432.
#define SCANL_SMEM ((16*520*2 + 2*36864) * 2)   // 180736 bytes

__global__ __launch_bounds__(256) void k_scan_local(int phase, float* __restrict__ hsp,
                                                    int hsmode)
{
    extern __shared__ __nv_bfloat16 sx[];
    const int tid  = threadIdx.x;
    const int lane = tid & 31;
    const int w    = tid >> 5;          // 0..7
    const int j    = blockIdx.x;        // chunk

    if (hsmode == 2) hsp = g_hs;

    const uint32_t s32  = smem_u32(sx);
    const uint32_t HLO  = 8320;         // halves
    const uint32_t AST  = 16640;        // halves

    // init H state
    if (phase == 0) {
        for (int e = tid; e < 8320; e += 256) ((uint32_t*)sx)[e] = 0u;   // 16640 halves
    } else {
        for (int e = tid; e < 2048; e += 256) {                          // 16x512 / 4
            int r  = e >> 7;
            int c4 = (e & 127) << 2;
            float4 v = *(const float4*)&g_Hi[((size_t)(j * 16 + r)) * HS + c4];
            uint2 h, l;
            split4(v, h, l);
            *(uint2*)&sx[r * 520 + c4]       = h;
            *(uint2*)&sx[HLO + r * 520 + c4] = l;
        }
    }
    __syncthreads();

    const uint32_t khalf = (uint32_t)((lane >> 4) << 3);
    const uint32_t hrow  = (uint32_t)(lane & 15);

    auto stage = [&](int p, int b) {
        const int kc = p >> 1, nh = p & 1;
        const size_t gh = (size_t)(nh * 256 + tid) * HS + kc * 64;
        const uint32_t d = s32 + (uint32_t)(AST + b * 36864 + tid * 72) * 2;
#pragma unroll
        for (int q = 0; q < 8; ++q) {
            cp16(d + q * 16,             g_Sah + gh + q * 8);
            cp16(d + 18432 * 2 + q * 16, g_Sal + gh + q * 8);
        }
    };

    for (int i = 0; i < LC; ++i) {
        float acc[2][4][4];
#pragma unroll
        for (int nh = 0; nh < 2; ++nh)
#pragma unroll
            for (int an = 0; an < 4; ++an)
#pragma unroll
                for (int q = 0; q < 4; ++q) acc[nh][an][q] = 0.f;

        const bool skip = (phase == 0) && (i == 0);   // H is all zeros
        if (!skip) {
            uint32_t fh[4][4], fl[4][4];
            stage(0, 0); CP_COMMIT();
            for (int p = 0; p < 16; ++p) {
                if (p < 15) { stage(p + 1, (p + 1) & 1); CP_COMMIT(); CP_WAIT(1); }
                else        { CP_WAIT(0); }
                __syncthreads();
                const int kc = p >> 1, nh = p & 1, b = p & 1;
                if (nh == 0) {
#pragma unroll
                    for (int ks = 0; ks < 4; ++ks) {
                        uint32_t off = s32 + (hrow * 520 + (uint32_t)(kc * 64 + ks * 16) + khalf) * 2;
                        ldmx4(fh[ks], off);
                        ldmx4(fl[ks], off + HLO * 2);
                    }
                }
                const uint32_t ab = AST + (uint32_t)(b * 36864);
#pragma unroll
                for (int ks = 0; ks < 4; ++ks) {
                    const uint32_t kcol = (uint32_t)(ks * 16) + khalf;
                    uint32_t bh[4][2], bl[4][2];
#pragma unroll
                    for (int nt = 0; nt < 2; ++nt) {
                        uint32_t off = s32 + (ab + (uint32_t)((w * 32 + nt * 16) + (lane & 15)) * 72 + kcol) * 2;
                        uint32_t qh[4], ql[4];
                        ldmx4(qh, off);
                        ldmx4(ql, off + 18432 * 2);
                        bh[2*nt+0][0] = qh[0]; bh[2*nt+0][1] = qh[2];
                        bh[2*nt+1][0] = qh[1]; bh[2*nt+1][1] = qh[3];
                        bl[2*nt+0][0] = ql[0]; bl[2*nt+0][1] = ql[2];
                        bl[2*nt+1][0] = ql[1]; bl[2*nt+1][1] = ql[3];
                    }
#pragma unroll
                    for (int an = 0; an < 4; ++an) {
                        mma16816(acc[nh][an], fh[ks], bh[an]);
                        mma16816(acc[nh][an], fh[ks], bl[an]);
                        mma16816(acc[nh][an], fl[ks], bh[an]);
                    }
                }
                __syncthreads();
            }
        }

        // epilogue: add bx, split back into H smem, conditional global outputs
        const float* bxs = g_bxc + (size_t)i * MR * HS + (size_t)j * 16 * HS;
        const int r0 = lane >> 2;
        const int r1 = r0 + 8;
        const bool wr_final = (phase == 0) && (i == LC - 1);
#pragma unroll
        for (int nh = 0; nh < 2; ++nh)
#pragma unroll
            for (int an = 0; an < 4; ++an) {
                int c = nh * 256 + w * 32 + (an >> 1) * 16 + (an & 1) * 8 + ((lane & 3) << 1);
                float2 b0 = *(const float2*)&bxs[(size_t)r0 * HS + c];
                float2 b1 = *(const float2*)&bxs[(size_t)r1 * HS + c];
                float v00 = acc[nh][an][0] + b0.x, v01 = acc[nh][an][1] + b0.y;
                float v10 = acc[nh][an][2] + b1.x, v11 = acc[nh][an][3] + b1.y;
                uint32_t h0, l0, h1, l1;
                split2(v00, v01, h0, l0);
                split2(v10, v11, h1, l1);
                *(uint32_t*)&sx[r0 * 520 + c]       = h0;
                *(uint32_t*)&sx[HLO + r0 * 520 + c] = l0;
                *(uint32_t*)&sx[r1 * 520 + c]       = h1;
                *(uint32_t*)&sx[HLO + r1 * 520 + c] = l1;
                if (wr_final) {
                    *(float2*)&g_H0[(size_t)(j * 16 + r0) * HS + c] = make_float2(v00, v01);
                    *(float2*)&g_H0[(size_t)(j * 16 + r1) * HS + c] = make_float2(v10, v11);
                }
                if (hsmode) {
                    size_t ho0 = ((size_t)r0 * SS + j * 16 + i) * HS + c;
                    size_t ho1 = ((size_t)r1 * SS + j * 16 + i) * HS + c;
                    *(float2*)&hsp[ho0] = make_float2(v00, v01);
                    *(float2*)&hsp[ho1] = make_float2(v10, v11);
                    *(uint32_t*)&g_Ahi[ho0] = h0;  *(uint32_t*)&g_Alo[ho0] = l0;
                    *(uint32_t*)&g_Ahi[ho1] = h1;  *(uint32_t*)&g_Alo[ho1] = l1;
                }
            }
        __syncthreads();   // H smem writes visible before next step's frag loads
    }
}

// ---------------- fused squarings: A^16 via 4 squarings, one launch ----------------
__global__ __launch_bounds__(128) void k_sq_fused(const float* __restrict__ A0)
{
    __shared__ float sI[16][68];
    __shared__ float sW[16][68];

    const int tid  = threadIdx.x;
    const int row0 = (blockIdx.x >> 3) << 6;
    const int col0 = (blockIdx.x & 7) << 6;
    const int lr   = tid >> 1;
    const int lk   = (tid & 1) << 3;
    const int kk2  = tid >> 4;
    const int nq   = (tid & 15) << 2;
    const int tx = tid & 7, ty = tid >> 3;

    for (int s = 0; s < 4; ++s) {        // A->P0(A^2)->P1(A^4)->P0(A^8)->P1(A^16)
        const float* X;
        float* Outp;
        if (s == 0)      { X = A0;   Outp = g_P0; }
        else if (s & 1)  { X = g_P0; Outp = g_P1; }
        else             { X = g_P1; Outp = g_P0; }

        const float* ip = X + (size_t)(row0 + lr) * HS + lk;

        float acc[4][8];
#pragma unroll
        for (int i = 0; i < 4; i++)
#pragma unroll
            for (int jq = 0; jq < 8; jq++) acc[i][jq] = 0.f;

        for (int k0 = 0; k0 < HS; k0 += 16) {
            float4 a0 = *(const float4*)(ip + k0);
            float4 a1 = *(const float4*)(ip + k0 + 4);
            float4 y0 = *(const float4*)&X[(size_t)(k0 + kk2)     * HS + col0 + nq];
            float4 y1 = *(const float4*)&X[(size_t)(k0 + kk2 + 8) * HS + col0 + nq];
            sI[lk+0][lr]=a0.x; sI[lk+1][lr]=a0.y; sI[lk+2][lr]=a0.z; sI[lk+3][lr]=a0.w;
            sI[lk+4][lr]=a1.x; sI[lk+5][lr]=a1.y; sI[lk+6][lr]=a1.z; sI[lk+7][lr]=a1.w;
            *(float4*)&sW[kk2][nq]     = y0;
            *(float4*)&sW[kk2 + 8][nq] = y1;
            __syncthreads();
#pragma unroll
            for (int k = 0; k < 16; k++) {
                float4 ri = *(const float4*)&sI[k][ty << 2];
                float4 w0 = *(const float4*)&sW[k][tx << 3];
                float4 w1 = *(const float4*)&sW[k][(tx << 3) + 4];
                float rr[4] = {ri.x, ri.y, ri.z, ri.w};
                float ww[8] = {w0.x, w0.y, w0.z, w0.w, w1.x, w1.y, w1.z, w1.w};
#pragma unroll
                for (int i = 0; i < 4; i++)
#pragma unroll
                    for (int jq = 0; jq < 8; jq++) acc[i][jq] += rr[i] * ww[jq];
            }
            __syncthreads();
        }
#pragma unroll
        for (int i = 0; i < 4; i++) {
            size_t o = (size_t)(row0 + (ty << 2) + i) * HS + col0 + (tx << 3);
            *(float4*)&Outp[o]     = make_float4(acc[i][0], acc[i][1], acc[i][2], acc[i][3]);
            *(float4*)&Outp[o + 4] = make_float4(acc[i][4], acc[i][5], acc[i][6], acc[i][7]);
        }
        gbar(&g_cntS, 64u * (unsigned)(s + 1));
    }
}

// ---------------- persistent cross-chunk scan (127 steps, matrix A^16) ----------------
__global__ __launch_bounds__(256) void k_cross_persist()
{
    __shared__ float sS[16][516];
    const float* AL = g_P1;              // A^16
    const int t  = threadIdx.x;
    const int n0 = blockIdx.x << 4;
    const int r  = t & 15;
    const int no = t >> 4;
    const int n  = n0 + no;
    const float* arow = AL + (size_t)n * HS;

    for (int j = 1; j < CC; ++j) {
        const float* sprev = g_Hi + (size_t)(j - 1) * BS * HS;
        const float* fprev = g_H0 + (size_t)(j - 1) * BS * HS;
        float*       sout  = g_Hi + (size_t)j * BS * HS;

        for (int e = t; e < BS * HS / 4; e += 256) {
            float4 v = ((const float4*)sprev)[e];
            int rr = e >> 7;
            int kk = (e & 127) << 2;
            *(float4*)&sS[rr][kk] = v;
        }
        __syncthreads();

        float a0 = 0.f, a1 = 0.f, a2 = 0.f, a3 = 0.f;
#pragma unroll 4
        for (int k = 0; k < HS; k += 16) {
            float4 v0 = *(const float4*)&arow[k];
            float4 v1 = *(const float4*)&arow[k + 4];
            float4 v2 = *(const float4*)&arow[k + 8];
            float4 v3 = *(const float4*)&arow[k + 12];
            a0 += v0.x*sS[r][k+0]  + v0.y*sS[r][k+1]  + v0.z*sS[r][k+2]  + v0.w*sS[r][k+3];
            a1 += v1.x*sS[r][k+4]  + v1.y*sS[r][k+5]  + v1.z*sS[r][k+6]  + v1.w*sS[r][k+7];
            a2 += v2.x*sS[r][k+8]  + v2.y*sS[r][k+9]  + v2.z*sS[r][k+10] + v2.w*sS[r][k+11];
            a3 += v3.x*sS[r][k+12] + v3.y*sS[r][k+13] + v3.z*sS[r][k+14] + v3.w*sS[r][k+15];
        }
        sout[(size_t)r * HS + n] = (a0 + a1) + (a2 + a3) + fprev[(size_t)r * HS + n];
        gbar(&g_cnt3, 32u * (unsigned)j);
    }
}

// ---------------- launch ----------------
extern "C" void kernel_launch(void* const* d_in, const int* in_sizes, int n_in,
                              void* d_out, int out_size)
{
    const float* x  = (const float*)d_in[0];
    const float* Aw = (const float*)d_in[1];
    const float* Bw = (const float*)d_in[2];
    const float* Cw = (const float*)d_in[3];
    float* out = (float*)d_out;

    const size_t YS = (size_t)BS * SS * HS;
    bool both = (size_t)out_size >= 2 * YS;     // output = (ys, hs) concatenated
    float* hsp = both ? out + YS : nullptr;
    int hsmode = both ? 1 : 2;

    cudaFuncSetAttribute(k_scan_local,
                         cudaFuncAttributeMaxDynamicSharedMemorySize, SCANL_SMEM);
    cudaFuncSetAttribute(k_gemm_mma,
                         cudaFuncAttributeMaxDynamicSharedMemorySize, GEMM_SMEM);

    // 0) zero chunk-initial states + counters
    k_zero<<<4096, 256>>>();

    // 1) splits: x (permuted), B weights, scan A weights
    k_split_x<<<GM, 128>>>(x);
    k_split_w<<<HS, 128>>>(Bw);
    k_split_A<<<HS, 128>>>(Aw);

    // 2) bx = x @ B^T via mma.sync bf16x3 -> g_bxc (step-major, LC=16 layout)
    k_gemm_mma<<<dim3(4, 256), 256, GEMM_SMEM>>>(nullptr, 1);

    // 3) A^16 by fused repeated squaring (result in g_P1)
    k_sq_fused<<<64, 128>>>(Aw);

    // 4) phase 1: CTA-local chunk scans (zero init) -> finals in g_H0
    k_scan_local<<<CC, 256, SCANL_SMEM>>>(0, nullptr, 0);

    // 5) phase 2: cross-chunk scan (127 steps, A^16)
    k_cross_persist<<<32, 256>>>();

    // 6) phase 3: CTA-local chunk scans from g_Hi, writes hs + ys-GEMM operands
    k_scan_local<<<CC, 256, SCANL_SMEM>>>(1, hsp, hsmode);

    // 7) split C weights, then ys = hs @ C^T via mma.sync bf16x3
    k_split_w<<<HS, 128>>>(Cw);
    k_gemm_mma<<<dim3(4, 256), 256, GEMM_SMEM>>>(out, 0);
}

// round 14
// speedup vs baseline: 1.6548x; 1.6548x over previous
#include <cuda_runtime.h>
#include <cuda_bf16.h>
#include <cstdint>
#include <cstddef>

#define HS 512
#define BS 16
#define SS 2048
#define LC 32              // chunk length
#define CC 64              // number of chunks
#define MR (CC*BS)         // 1024 rows per scan step
#define GM 32768           // big-GEMM M (BS*SS)

// ---------------- scratch (static __device__; no allocation anywhere) ----------------
static __device__ float g_bxc[(size_t)SS * BS * HS];   // [i][chunk][b][h]
static __device__ float g_hs [(size_t)BS * SS * HS];   // fallback hs storage
static __device__ float g_H0[MR * HS];                 // fp32 states
static __device__ float g_H1[MR * HS];
static __device__ float g_Hi[MR * HS];                 // chunk initial states
static __device__ float g_P0[HS * HS];
static __device__ float g_P1[HS * HS];
static __device__ __nv_bfloat16 g_Ahi[(size_t)GM * HS];  // big-GEMM A operand hi
static __device__ __nv_bfloat16 g_Alo[(size_t)GM * HS];  // big-GEMM A operand lo
static __device__ __nv_bfloat16 g_Whi[HS * HS];          // B weight split
static __device__ __nv_bfloat16 g_Wlo[HS * HS];
static __device__ __nv_bfloat16 g_Chi[HS * HS];          // C weight split
static __device__ __nv_bfloat16 g_Clo[HS * HS];
static __device__ __nv_bfloat16 g_Hbh0[MR * HS];       // scan H bf16 hi, buf 0
static __device__ __nv_bfloat16 g_Hbl0[MR * HS];       // scan H bf16 lo, buf 0
static __device__ __nv_bfloat16 g_Hbh1[MR * HS];       // buf 1
static __device__ __nv_bfloat16 g_Hbl1[MR * HS];
static __device__ unsigned g_cntA[16];                 // per-row-tile scan barrier
static __device__ unsigned g_cnt3;                     // cross-scan barrier
static __device__ unsigned g_cntS;                     // fused-squaring barrier

// ---------------- warp MMA helpers (sm_80-era, valid on sm_100 base) ----------------
__device__ __forceinline__ uint32_t smem_u32(const void* p) {
    uint32_t a;
    asm("{ .reg .u64 t; cvta.to.shared.u64 t, %1; cvt.u32.u64 %0, t; }" : "=r"(a) : "l"(p));
    return a;
}
__device__ __forceinline__ void ldmx4(uint32_t* r, uint32_t addr)
{
    asm volatile("ldmatrix.sync.aligned.m8n8.x4.shared.b16 {%0,%1,%2,%3}, [%4];"
        : "=r"(r[0]), "=r"(r[1]), "=r"(r[2]), "=r"(r[3]) : "r"(addr));
}
__device__ __forceinline__ void mma16816(float* c, const uint32_t* a, const uint32_t* b)
{
    asm volatile(
        "mma.sync.aligned.m16n8k16.row.col.f32.bf16.bf16.f32 "
        "{%0,%1,%2,%3}, {%4,%5,%6,%7}, {%8,%9}, {%0,%1,%2,%3};"
        : "+f"(c[0]), "+f"(c[1]), "+f"(c[2]), "+f"(c[3])
        : "r"(a[0]), "r"(a[1]), "r"(a[2]), "r"(a[3]), "r"(b[0]), "r"(b[1]));
}

// ---------------- fp32 -> bf16 hi/lo splits ----------------
__device__ __forceinline__ void split4(float4 v, uint2& h, uint2& l)
{
    __nv_bfloat162 h01 = __floats2bfloat162_rn(v.x, v.y);
    __nv_bfloat162 h23 = __floats2bfloat162_rn(v.z, v.w);
    float2 f01 = __bfloat1622float2(h01);
    float2 f23 = __bfloat1622float2(h23);
    __nv_bfloat162 l01 = __floats2bfloat162_rn(v.x - f01.x, v.y - f01.y);
    __nv_bfloat162 l23 = __floats2bfloat162_rn(v.z - f23.x, v.w - f23.y);
    h.x = *reinterpret_cast<uint32_t*>(&h01);
    h.y = *reinterpret_cast<uint32_t*>(&h23);
    l.x = *reinterpret_cast<uint32_t*>(&l01);
    l.y = *reinterpret_cast<uint32_t*>(&l23);
}
__device__ __forceinline__ void split2(float a, float b, uint32_t& h, uint32_t& l)
{
    __nv_bfloat162 hh = __floats2bfloat162_rn(a, b);
    float2 f = __bfloat1622float2(hh);
    __nv_bfloat162 ll = __floats2bfloat162_rn(a - f.x, b - f.y);
    h = *reinterpret_cast<uint32_t*>(&hh);
    l = *reinterpret_cast<uint32_t*>(&ll);
}

// ---------------- global barrier (co-resident grids only) ----------------
__device__ __forceinline__ void gbar(unsigned* cnt, unsigned target)
{
    __threadfence();
    __syncthreads();
    if (threadIdx.x == 0) {
        atomicAdd(cnt, 1u);
        while (*(volatile unsigned*)cnt < target) { __nanosleep(40); }
        __threadfence();
    }
    __syncthreads();
}

// ---------------- fused init: zero buffers + split x, B, C ----------------
// grid layout: [0,32768) x rows; [32768,33280) B rows; [33280,33792) C rows;
//              [33792,34816) zero blocks
__global__ __launch_bounds__(128) void k_init(const float* __restrict__ x,
                                              const float* __restrict__ Bw,
                                              const float* __restrict__ Cw)
{
    const int bid = blockIdx.x;
    const int tid = threadIdx.x;

    if (bid < 32768) {                        // split x (row-permuted)
        int r  = bid;
        int ii = r >> 10;
        int jb = r & 1023;
        int srow = (jb & 15) * SS + ((jb >> 4) << 5) + ii;
        int c = tid << 2;
        float4 v = *(const float4*)&x[(size_t)srow * HS + c];
        uint2 h, l;
        split4(v, h, l);
        *(uint2*)&g_Ahi[(size_t)r * HS + c] = h;
        *(uint2*)&g_Alo[(size_t)r * HS + c] = l;
    } else if (bid < 33280) {                 // split B
        int r = bid - 32768;
        int c = tid << 2;
        float4 v = *(const float4*)&Bw[(size_t)r * HS + c];
        uint2 h, l;
        split4(v, h, l);
        *(uint2*)&g_Whi[(size_t)r * HS + c] = h;
        *(uint2*)&g_Wlo[(size_t)r * HS + c] = l;
    } else if (bid < 33792) {                 // split C
        int r = bid - 33280;
        int c = tid << 2;
        float4 v = *(const float4*)&Cw[(size_t)r * HS + c];
        uint2 h, l;
        split4(v, h, l);
        *(uint2*)&g_Chi[(size_t)r * HS + c] = h;
        *(uint2*)&g_Clo[(size_t)r * HS + c] = l;
    } else {                                  // zero blocks
        int e = (bid - 33792) * 128 + tid;    // 0..131071
        float4 z4 = make_float4(0.f, 0.f, 0.f, 0.f);
        ((float4*)g_H0)[e] = z4;
        ((float4*)g_Hi)[e] = z4;
        if (e < 65536) ((uint4*)g_Hbh0)[e] = make_uint4(0u, 0u, 0u, 0u);
        else           ((uint4*)g_Hbl0)[e - 65536] = make_uint4(0u, 0u, 0u, 0u);
        if (bid == 33792) {
            if (tid < 16) g_cntA[tid] = 0u;
            if (tid == 16) g_cnt3 = 0u;
            if (tid == 17) g_cntS = 0u;
        }
    }
}

// split g_Hi (cross-scan output) into scan bf16 buf 0
__global__ __launch_bounds__(128) void k_split_hi()
{
    int r = blockIdx.x;
    int c = threadIdx.x << 2;
    float4 v = *(const float4*)&g_Hi[(size_t)r * HS + c];
    uint2 h, l;
    split4(v, h, l);
    *(uint2*)&g_Hbh0[(size_t)r * HS + c] = h;
    *(uint2*)&g_Hbl0[(size_t)r * HS + c] = l;
}

// ---------------- bf16x3 big GEMM via mma.sync (proven 220us config) ----------------
#define GEMM_SMEM (4 * 128 * 72 * 2)     // 73728 bytes

__global__ __launch_bounds__(256) void k_gemm_mma(float* __restrict__ Out, int mode, int wsel)
{
    if (mode == 1) Out = g_bxc;
    const __nv_bfloat16* Wh = wsel ? g_Chi : g_Whi;
    const __nv_bfloat16* Wl = wsel ? g_Clo : g_Wlo;

    extern __shared__ __nv_bfloat16 sb[];
    __nv_bfloat16* sAh = sb;
    __nv_bfloat16* sAl = sb + 9216;
    __nv_bfloat16* sWh = sb + 18432;
    __nv_bfloat16* sWl = sb + 27648;

    const int tid  = threadIdx.x;
    const int lane = tid & 31;
    const int wid  = tid >> 5;
    const int row0 = blockIdx.y << 7;
    const int col0 = blockIdx.x << 7;
    const int wm   = wid >> 2;
    const int wn   = wid & 3;

    const int lrow = tid >> 1;
    const int lseg = (tid & 1) << 5;

    float acc[4][4][4];
#pragma unroll
    for (int mt = 0; mt < 4; ++mt)
#pragma unroll
        for (int nt = 0; nt < 4; ++nt)
#pragma unroll
            for (int q = 0; q < 4; ++q) acc[mt][nt][q] = 0.f;

    const uint32_t sAh32 = smem_u32(sAh);
    const uint32_t sAl32 = smem_u32(sAl);
    const uint32_t sWh32 = smem_u32(sWh);
    const uint32_t sWl32 = smem_u32(sWl);

    const uint32_t a_lrow = (uint32_t)(wm * 64 + (lane & 15));
    const uint32_t b_lrow = (uint32_t)(wn * 32 + (lane & 15));
    const uint32_t khalf  = (uint32_t)((lane >> 4) << 3);

    for (int kc = 0; kc < 8; ++kc) {
        __syncthreads();
        {
            const size_t gA = (size_t)(row0 + lrow) * HS + kc * 64 + lseg;
            const size_t gW = (size_t)(col0 + lrow) * HS + kc * 64 + lseg;
            const uint32_t so = (uint32_t)(lrow * 72 + lseg);
#pragma unroll
            for (int i = 0; i < 4; ++i) {
                *(uint4*)(sAh + so + i*8) = *(const uint4*)(g_Ahi + gA + i*8);
                *(uint4*)(sAl + so + i*8) = *(const uint4*)(g_Alo + gA + i*8);
                *(uint4*)(sWh + so + i*8) = *(const uint4*)(Wh + gW + i*8);
                *(uint4*)(sWl + so + i*8) = *(const uint4*)(Wl + gW + i*8);
            }
        }
        __syncthreads();

#pragma unroll
        for (int ks = 0; ks < 4; ++ks) {
            const uint32_t kcol = (uint32_t)(ks * 16) + khalf;
            uint32_t ah[4][4], al[4][4], bh[4][2], bl[4][2];
#pragma unroll
            for (int mt = 0; mt < 4; ++mt) {
                uint32_t off = ((a_lrow + mt*16) * 72 + kcol) * 2;
                ldmx4(ah[mt], sAh32 + off);
                ldmx4(al[mt], sAl32 + off);
            }
#pragma unroll
            for (int bt = 0; bt < 2; ++bt) {
                uint32_t off = ((b_lrow + bt*16) * 72 + kcol) * 2;
                uint32_t qh[4], ql[4];
                ldmx4(qh, sWh32 + off);
                ldmx4(ql, sWl32 + off);
                bh[2*bt+0][0] = qh[0]; bh[2*bt+0][1] = qh[2];
                bh[2*bt+1][0] = qh[1]; bh[2*bt+1][1] = qh[3];
                bl[2*bt+0][0] = ql[0]; bl[2*bt+0][1] = ql[2];
                bl[2*bt+1][0] = ql[1]; bl[2*bt+1][1] = ql[3];
            }
#pragma unroll
            for (int mt = 0; mt < 4; ++mt)
#pragma unroll
                for (int nt = 0; nt < 4; ++nt) {
                    mma16816(acc[mt][nt], ah[mt], bh[nt]);
                    mma16816(acc[mt][nt], ah[mt], bl[nt]);
                    mma16816(acc[mt][nt], al[mt], bh[nt]);
                }
        }
    }

    const int r_base = row0 + wm * 64 + (lane >> 2);
    const int c_base = col0 + wn * 32 + ((lane & 3) << 1);
#pragma unroll
    for (int mt = 0; mt < 4; ++mt)
#pragma unroll
        for (int nt = 0; nt < 4; ++nt) {
            size_t o0 = (size_t)(r_base + mt*16)     * HS + c_base + nt*8;
            size_t o1 = (size_t)(r_base + mt*16 + 8) * HS + c_base + nt*8;
            *(float2*)&Out[o0] = make_float2(acc[mt][nt][0], acc[mt][nt][1]);
            *(float2*)&Out[o1] = make_float2(acc[mt][nt][2], acc[mt][nt][3]);
        }
}

// ---------------- persistent tensor-core scan (round-9 proven) ----------------
#define SCANT_SMEM ((8*64*72*2 + 64*72*2) * 2)   // 165888 bytes

__global__ __launch_bounds__(256) void k_scan_mma(int phase, float* __restrict__ hsp,
                                                  int hsmode, const float* __restrict__ Aw)
{
    extern __shared__ __nv_bfloat16 sx[];
    __nv_bfloat16* sAh = sx;                       // [8][64][72]
    __nv_bfloat16* sAl = sx + 36864;
    __nv_bfloat16* sHh = sx + 73728;               // [64][72]
    __nv_bfloat16* sHl = sx + 73728 + 4608;

    const int tid  = threadIdx.x;
    const int lane = tid & 31;
    const int wid  = tid >> 5;
    const int wm   = wid >> 2;          // 0..1
    const int wn   = wid & 3;           // 0..3
    const int col0 = blockIdx.x << 6;
    const int rb   = blockIdx.y;
    const int row0 = rb << 6;

    if (hsmode == 2) hsp = g_hs;

    // one-time: split A rows [col0, col0+64) into resident bf16 hi/lo
    for (int e = tid; e < 64 * 128; e += 256) {
        int row = e >> 7;
        int c4  = (e & 127) << 2;
        float4 v = *(const float4*)&Aw[(size_t)(col0 + row) * HS + c4];
        uint2 h, l;
        split4(v, h, l);
        int off = ((c4 >> 6) * 4608) + row * 72 + (c4 & 63);
        *(uint2*)&sAh[off] = h;
        *(uint2*)&sAl[off] = l;
    }
    __syncthreads();

    const uint32_t sAh32 = smem_u32(sAh), sAl32 = smem_u32(sAl);
    const uint32_t sHh32 = smem_u32(sHh), sHl32 = smem_u32(sHl);

    const uint32_t a_lrow = (uint32_t)(wm * 32 + (lane & 15));
    const uint32_t b_lrow = (uint32_t)(wn * 16 + (lane & 15));
    const uint32_t khalf  = (uint32_t)((lane >> 4) << 3);
    const int srow = tid >> 2;           // stage row 0..63
    const int sseg = (tid & 3) << 4;     // stage seg 0/16/32/48 halves

    const unsigned base = phase ? (8u * LC) : 0u;
    unsigned* cnt = &g_cntA[rb];

    for (int i = 0; i < LC; ++i) {
        const __nv_bfloat16* Hh = (i & 1) ? g_Hbh1 : g_Hbh0;
        const __nv_bfloat16* Hl = (i & 1) ? g_Hbl1 : g_Hbl0;
        __nv_bfloat16* Oh = (i & 1) ? g_Hbh0 : g_Hbh1;
        __nv_bfloat16* Ol = (i & 1) ? g_Hbl0 : g_Hbl1;
        float* Hout = (i & 1) ? g_H0 : g_H1;     // fp32 states (finals for cross)
        const float* bxs = g_bxc + (size_t)i * MR * HS;

        float acc[2][2][4];
#pragma unroll
        for (int mt = 0; mt < 2; ++mt)
#pragma unroll
            for (int nt = 0; nt < 2; ++nt)
#pragma unroll
                for (int q = 0; q < 4; ++q) acc[mt][nt][q] = 0.f;

        const bool skip = (phase == 0) && (i == 0);   // H input is all zeros
        if (!skip) {
            for (int kc = 0; kc < 8; ++kc) {
                __syncthreads();
                {
                    size_t g = (size_t)(row0 + srow) * HS + kc * 64 + sseg;
                    int so = srow * 72 + sseg;
                    *(uint4*)&sHh[so]     = *(const uint4*)&Hh[g];
                    *(uint4*)&sHh[so + 8] = *(const uint4*)&Hh[g + 8];
                    *(uint4*)&sHl[so]     = *(const uint4*)&Hl[g];
                    *(uint4*)&sHl[so + 8] = *(const uint4*)&Hl[g + 8];
                }
                __syncthreads();
                const uint32_t bbase = (uint32_t)(kc * 4608);
#pragma unroll
                for (int ks = 0; ks < 4; ++ks) {
                    const uint32_t kcol = (uint32_t)(ks * 16) + khalf;
                    uint32_t ah[2][4], al[2][4];
#pragma unroll
                    for (int mt = 0; mt < 2; ++mt) {
                        uint32_t off = ((a_lrow + mt*16) * 72 + kcol) * 2;
                        ldmx4(ah[mt], sHh32 + off);
                        ldmx4(al[mt], sHl32 + off);
                    }
                    uint32_t qh[4], ql[4];
                    {
                        uint32_t off = (bbase + b_lrow * 72 + kcol) * 2;
                        ldmx4(qh, sAh32 + off);
                        ldmx4(ql, sAl32 + off);
                    }
                    uint32_t bh[2][2] = {{qh[0], qh[2]}, {qh[1], qh[3]}};
                    uint32_t bl[2][2] = {{ql[0], ql[2]}, {ql[1], ql[3]}};
#pragma unroll
                    for (int mt = 0; mt < 2; ++mt)
#pragma unroll
                        for (int nt = 0; nt < 2; ++nt) {
                            mma16816(acc[mt][nt], ah[mt], bh[nt]);
                            mma16816(acc[mt][nt], ah[mt], bl[nt]);
                            mma16816(acc[mt][nt], al[mt], bh[nt]);
                        }
                }
            }
        }

        // epilogue: add bx, write fp32 state + bf16 pair (+ hs outputs in phase 3)
        const int r_b = row0 + wm * 32 + (lane >> 2);
        const int c_b = col0 + wn * 16 + ((lane & 3) << 1);
#pragma unroll
        for (int mt = 0; mt < 2; ++mt)
#pragma unroll
            for (int nt = 0; nt < 2; ++nt) {
                int r0 = r_b + mt * 16;
                int c  = c_b + nt * 8;
                size_t o0 = (size_t)r0 * HS + c;
                size_t o1 = (size_t)(r0 + 8) * HS + c;
                float2 b0 = *(const float2*)&bxs[o0];
                float2 b1 = *(const float2*)&bxs[o1];
                float v00 = acc[mt][nt][0] + b0.x, v01 = acc[mt][nt][1] + b0.y;
                float v10 = acc[mt][nt][2] + b1.x, v11 = acc[mt][nt][3] + b1.y;
                *(float2*)&Hout[o0] = make_float2(v00, v01);
                *(float2*)&Hout[o1] = make_float2(v10, v11);
                uint32_t h0, l0, h1, l1;
                split2(v00, v01, h0, l0);
                split2(v10, v11, h1, l1);
                *(uint32_t*)&Oh[o0] = h0;  *(uint32_t*)&Ol[o0] = l0;
                *(uint32_t*)&Oh[o1] = h1;  *(uint32_t*)&Ol[o1] = l1;
                if (hsmode) {
                    size_t ho0 = ((size_t)(r0 & 15) * SS + ((r0 >> 4) << 5) + i) * HS + c;
                    int r1 = r0 + 8;
                    size_t ho1 = ((size_t)(r1 & 15) * SS + ((r1 >> 4) << 5) + i) * HS + c;
                    *(float2*)&hsp[ho0] = make_float2(v00, v01);
                    *(float2*)&hsp[ho1] = make_float2(v10, v11);
                    *(uint32_t*)&g_Ahi[ho0] = h0;  *(uint32_t*)&g_Alo[ho0] = l0;
                    *(uint32_t*)&g_Ahi[ho1] = h1;  *(uint32_t*)&g_Alo[ho1] = l1;
                }
            }
        gbar(cnt, base + 8u * (i + 1));
    }
}

// ---------------- fused squarings: A^32 via 5 squarings, one launch ----------------
__global__ __launch_bounds__(128) void k_sq_fused(const float* __restrict__ A0)
{
    __shared__ float sI[16][68];
    __shared__ float sW[16][68];

    const int tid  = threadIdx.x;
    const int row0 = (blockIdx.x >> 3) << 6;
    const int col0 = (blockIdx.x & 7) << 6;
    const int lr   = tid >> 1;
    const int lk   = (tid & 1) << 3;
    const int kk2  = tid >> 4;
    const int nq   = (tid & 15) << 2;
    const int tx = tid & 7, ty = tid >> 3;

    for (int s = 0; s < 5; ++s) {
        const float* X;
        float* Outp;
        if (s == 0)      { X = A0;   Outp = g_P0; }
        else if (s & 1)  { X = g_P0; Outp = g_P1; }
        else             { X = g_P1; Outp = g_P0; }

        const float* ip = X + (size_t)(row0 + lr) * HS + lk;

        float acc[4][8];
#pragma unroll
        for (int i = 0; i < 4; i++)
#pragma unroll
            for (int j = 0; j < 8; j++) acc[i][j] = 0.f;

        for (int k0 = 0; k0 < HS; k0 += 16) {
            float4 a0 = *(const float4*)(ip + k0);
            float4 a1 = *(const float4*)(ip + k0 + 4);
            float4 y0 = *(const float4*)&X[(size_t)(k0 + kk2)     * HS + col0 + nq];
            float4 y1 = *(const float4*)&X[(size_t)(k0 + kk2 + 8) * HS + col0 + nq];
            sI[lk+0][lr]=a0.x; sI[lk+1][lr]=a0.y; sI[lk+2][lr]=a0.z; sI[lk+3][lr]=a0.w;
            sI[lk+4][lr]=a1.x; sI[lk+5][lr]=a1.y; sI[lk+6][lr]=a1.z; sI[lk+7][lr]=a1.w;
            *(float4*)&sW[kk2][nq]     = y0;
            *(float4*)&sW[kk2 + 8][nq] = y1;
            __syncthreads();
#pragma unroll
            for (int k = 0; k < 16; k++) {
                float4 ri = *(const float4*)&sI[k][ty << 2];
                float4 w0 = *(const float4*)&sW[k][tx << 3];
                float4 w1 = *(const float4*)&sW[k][(tx << 3) + 4];
                float rr[4] = {ri.x, ri.y, ri.z, ri.w};
                float ww[8] = {w0.x, w0.y, w0.z, w0.w, w1.x, w1.y, w1.z, w1.w};
#pragma unroll
                for (int i = 0; i < 4; i++)
#pragma unroll
                    for (int j = 0; j < 8; j++) acc[i][j] += rr[i] * ww[j];
            }
            __syncthreads();
        }
#pragma unroll
        for (int i = 0; i < 4; i++) {
            size_t o = (size_t)(row0 + (ty << 2) + i) * HS + col0 + (tx << 3);
            *(float4*)&Outp[o]     = make_float4(acc[i][0], acc[i][1], acc[i][2], acc[i][3]);
            *(float4*)&Outp[o + 4] = make_float4(acc[i][4], acc[i][5], acc[i][6], acc[i][7]);
        }
        gbar(&g_cntS, 64u * (unsigned)(s + 1));
    }
}

// ---------------- persistent cross-chunk scan ----------------
__global__ __launch_bounds__(256) void k_cross_persist()
{
    __shared__ float sS[16][516];
    const float* AL = g_P0;              // A^32
    const int t  = threadIdx.x;
    const int n0 = blockIdx.x << 4;
    const int r  = t & 15;
    const int no = t >> 4;
    const int n  = n0 + no;
    const float* arow = AL + (size_t)n * HS;

    for (int j = 1; j < CC; ++j) {
        const float* sprev = g_Hi + (size_t)(j - 1) * BS * HS;
        const float* fprev = g_H0 + (size_t)(j - 1) * BS * HS;
        float*       sout  = g_Hi + (size_t)j * BS * HS;

        for (int e = t; e < BS * HS / 4; e += 256) {
            float4 v = ((const float4*)sprev)[e];
            int rr = e >> 7;
            int kk = (e & 127) << 2;
            *(float4*)&sS[rr][kk] = v;
        }
        __syncthreads();

        float a0 = 0.f, a1 = 0.f, a2 = 0.f, a3 = 0.f;
#pragma unroll 4
        for (int k = 0; k < HS; k += 16) {
            float4 v0 = *(const float4*)&arow[k];
            float4 v1 = *(const float4*)&arow[k + 4];
            float4 v2 = *(const float4*)&arow[k + 8];
            float4 v3 = *(const float4*)&arow[k + 12];
            a0 += v0.x*sS[r][k+0]  + v0.y*sS[r][k+1]  + v0.z*sS[r][k+2]  + v0.w*sS[r][k+3];
            a1 += v1.x*sS[r][k+4]  + v1.y*sS[r][k+5]  + v1.z*sS[r][k+6]  + v1.w*sS[r][k+7];
            a2 += v2.x*sS[r][k+8]  + v2.y*sS[r][k+9]  + v2.z*sS[r][k+10] + v2.w*sS[r][k+11];
            a3 += v3.x*sS[r][k+12] + v3.y*sS[r][k+13] + v3.z*sS[r][k+14] + v3.w*sS[r][k+15];
        }
        sout[(size_t)r * HS + n] = (a0 + a1) + (a2 + a3) + fprev[(size_t)r * HS + n];
        gbar(&g_cnt3, 32u * (unsigned)j);
    }
}

// ---------------- launch ----------------
extern "C" void kernel_launch(void* const* d_in, const int* in_sizes, int n_in,
                              void* d_out, int out_size)
{
    const float* x  = (const float*)d_in[0];
    const float* Aw = (const float*)d_in[1];
    const float* Bw = (const float*)d_in[2];
    const float* Cw = (const float*)d_in[3];
    float* out = (float*)d_out;

    const size_t YS = (size_t)BS * SS * HS;
    bool both = (size_t)out_size >= 2 * YS;     // output = (ys, hs) concatenated
    float* hsp = both ? out + YS : nullptr;
    int hsmode = both ? 1 : 2;

    cudaFuncSetAttribute(k_scan_mma,
                         cudaFuncAttributeMaxDynamicSharedMemorySize, SCANT_SMEM);
    cudaFuncSetAttribute(k_gemm_mma,
                         cudaFuncAttributeMaxDynamicSharedMemorySize, GEMM_SMEM);

    // 0) fused: zero buffers + split x/B/C
    k_init<<<34816, 128>>>(x, Bw, Cw);

    // 1) bx = x @ B^T via mma.sync bf16x3 -> g_bxc
    k_gemm_mma<<<dim3(4, 256), 256, GEMM_SMEM>>>(nullptr, 1, 0);

    // 2) A^32 by fused repeated squaring
    k_sq_fused<<<64, 128>>>(Aw);

    // 3) phase 1: tensor-core local scans (zero init)  [ncu profiles this launch]
    k_scan_mma<<<dim3(8, 16), 256, SCANT_SMEM>>>(0, nullptr, 0, Aw);

    // 4) phase 2: cross-chunk scan, persistent
    k_cross_persist<<<32, 256>>>();

    // 5) seed phase-3 initial states (bf16 split of g_Hi)
    k_split_hi<<<MR, 128>>>();

    // 6) phase 3: tensor-core local scans, writes hs + ys-GEMM operands
    k_scan_mma<<<dim3(8, 16), 256, SCANT_SMEM>>>(1, hsp, hsmode, Aw);

    // 7) ys = hs @ C^T via mma.sync bf16x3 (C split done in k_init)
    k_gemm_mma<<<dim3(4, 256), 256, GEMM_SMEM>>>(out, 0, 1);
}

// round 16
// speedup vs baseline: 1.7886x; 1.0808x over previous
#include <cuda_runtime.h>
#include <cuda_bf16.h>
#include <cstdint>
#include <cstddef>

#define HS 512
#define BS 16
#define SS 2048
#define LC 32              // chunk length
#define CC 64              // number of chunks
#define MR (CC*BS)         // 1024 rows per scan step
#define GM 32768           // big-GEMM M (BS*SS)

// ---------------- scratch (static __device__; no allocation anywhere) ----------------
static __device__ float g_bxc[(size_t)SS * BS * HS];   // [i][chunk][b][h]
static __device__ float g_hs [(size_t)BS * SS * HS];   // fallback hs storage
static __device__ float g_H0[MR * HS];                 // phase-1 finals (fp32)
static __device__ float g_Hi[MR * HS];                 // chunk initial states
static __device__ float g_P0[HS * HS];
static __device__ float g_P1[HS * HS];
static __device__ __nv_bfloat16 g_Ahi[(size_t)GM * HS];  // big-GEMM A operand hi
static __device__ __nv_bfloat16 g_Alo[(size_t)GM * HS];  // big-GEMM A operand lo
static __device__ __nv_bfloat16 g_Whi[HS * HS];          // B weight split
static __device__ __nv_bfloat16 g_Wlo[HS * HS];
static __device__ __nv_bfloat16 g_Chi[HS * HS];          // C weight split
static __device__ __nv_bfloat16 g_Clo[HS * HS];
static __device__ __nv_bfloat16 g_Hbh0[MR * HS];       // scan H bf16 hi, buf 0
static __device__ __nv_bfloat16 g_Hbl0[MR * HS];       // scan H bf16 lo, buf 0
static __device__ __nv_bfloat16 g_Hbh1[MR * HS];       // buf 1
static __device__ __nv_bfloat16 g_Hbl1[MR * HS];
static __device__ unsigned g_cntA[16];                 // per-row-tile scan barrier
static __device__ unsigned g_cnt3;                     // cross-scan barrier
static __device__ unsigned g_cntS;                     // fused-squaring barrier

// ---------------- warp MMA + cp.async helpers ----------------
__device__ __forceinline__ uint32_t smem_u32(const void* p) {
    uint32_t a;
    asm("{ .reg .u64 t; cvta.to.shared.u64 t, %1; cvt.u32.u64 %0, t; }" : "=r"(a) : "l"(p));
    return a;
}
__device__ __forceinline__ void ldmx4(uint32_t* r, uint32_t addr)
{
    asm volatile("ldmatrix.sync.aligned.m8n8.x4.shared.b16 {%0,%1,%2,%3}, [%4];"
        : "=r"(r[0]), "=r"(r[1]), "=r"(r[2]), "=r"(r[3]) : "r"(addr));
}
__device__ __forceinline__ void mma16816(float* c, const uint32_t* a, const uint32_t* b)
{
    asm volatile(
        "mma.sync.aligned.m16n8k16.row.col.f32.bf16.bf16.f32 "
        "{%0,%1,%2,%3}, {%4,%5,%6,%7}, {%8,%9}, {%0,%1,%2,%3};"
        : "+f"(c[0]), "+f"(c[1]), "+f"(c[2]), "+f"(c[3])
        : "r"(a[0]), "r"(a[1]), "r"(a[2]), "r"(a[3]), "r"(b[0]), "r"(b[1]));
}
__device__ __forceinline__ void cp16(uint32_t d, const void* s)
{
    asm volatile("{ .reg .u64 g; cvta.to.global.u64 g, %1; "
                 "cp.async.cg.shared.global [%0], [g], 16; }"
                 :: "r"(d), "l"(s) : "memory");
}
#define CP_COMMIT() asm volatile("cp.async.commit_group;" ::: "memory")
#define CP_WAIT(n)  asm volatile("cp.async.wait_group %0;" :: "n"(n) : "memory")

// ---------------- fp32 -> bf16 hi/lo splits ----------------
__device__ __forceinline__ void split4(float4 v, uint2& h, uint2& l)
{
    __nv_bfloat162 h01 = __floats2bfloat162_rn(v.x, v.y);
    __nv_bfloat162 h23 = __floats2bfloat162_rn(v.z, v.w);
    float2 f01 = __bfloat1622float2(h01);
    float2 f23 = __bfloat1622float2(h23);
    __nv_bfloat162 l01 = __floats2bfloat162_rn(v.x - f01.x, v.y - f01.y);
    __nv_bfloat162 l23 = __floats2bfloat162_rn(v.z - f23.x, v.w - f23.y);
    h.x = *reinterpret_cast<uint32_t*>(&h01);
    h.y = *reinterpret_cast<uint32_t*>(&h23);
    l.x = *reinterpret_cast<uint32_t*>(&l01);
    l.y = *reinterpret_cast<uint32_t*>(&l23);
}
__device__ __forceinline__ void split2(float a, float b, uint32_t& h, uint32_t& l)
{
    __nv_bfloat162 hh = __floats2bfloat162_rn(a, b);
    float2 f = __bfloat1622float2(hh);
    __nv_bfloat162 ll = __floats2bfloat162_rn(a - f.x, b - f.y);
    h = *reinterpret_cast<uint32_t*>(&hh);
    l = *reinterpret_cast<uint32_t*>(&ll);
}

// ---------------- global barrier (co-resident grids only) ----------------
__device__ __forceinline__ void gbar(unsigned* cnt, unsigned target)
{
    __threadfence();
    __syncthreads();
    if (threadIdx.x == 0) {
        atomicAdd(cnt, 1u);
        while (*(volatile unsigned*)cnt < target) { __nanosleep(40); }
        __threadfence();
    }
    __syncthreads();
}

// ---------------- fused init: zero buffers + split x, B, C ----------------
// grid layout: [0,32768) x rows; [32768,33280) B rows; [33280,33792) C rows;
//              [33792,34816) zero blocks
__global__ __launch_bounds__(128) void k_init(const float* __restrict__ x,
                                              const float* __restrict__ Bw,
                                              const float* __restrict__ Cw)
{
    const int bid = blockIdx.x;
    const int tid = threadIdx.x;

    if (bid < 32768) {                        // split x (row-permuted)
        int r  = bid;
        int ii = r >> 10;
        int jb = r & 1023;
        int srow = (jb & 15) * SS + ((jb >> 4) << 5) + ii;
        int c = tid << 2;
        float4 v = *(const float4*)&x[(size_t)srow * HS + c];
        uint2 h, l;
        split4(v, h, l);
        *(uint2*)&g_Ahi[(size_t)r * HS + c] = h;
        *(uint2*)&g_Alo[(size_t)r * HS + c] = l;
    } else if (bid < 33280) {                 // split B
        int r = bid - 32768;
        int c = tid << 2;
        float4 v = *(const float4*)&Bw[(size_t)r * HS + c];
        uint2 h, l;
        split4(v, h, l);
        *(uint2*)&g_Whi[(size_t)r * HS + c] = h;
        *(uint2*)&g_Wlo[(size_t)r * HS + c] = l;
    } else if (bid < 33792) {                 // split C
        int r = bid - 33280;
        int c = tid << 2;
        float4 v = *(const float4*)&Cw[(size_t)r * HS + c];
        uint2 h, l;
        split4(v, h, l);
        *(uint2*)&g_Chi[(size_t)r * HS + c] = h;
        *(uint2*)&g_Clo[(size_t)r * HS + c] = l;
    } else {                                  // zero blocks
        int e = (bid - 33792) * 128 + tid;    // 0..131071
        float4 z4 = make_float4(0.f, 0.f, 0.f, 0.f);
        ((float4*)g_H0)[e] = z4;
        ((float4*)g_Hi)[e] = z4;
        if (e < 65536) ((uint4*)g_Hbh0)[e] = make_uint4(0u, 0u, 0u, 0u);
        else           ((uint4*)g_Hbl0)[e - 65536] = make_uint4(0u, 0u, 0u, 0u);
        if (bid == 33792) {
            if (tid < 16) g_cntA[tid] = 0u;
            if (tid == 16) g_cnt3 = 0u;
            if (tid == 17) g_cntS = 0u;
        }
    }
}

// split g_Hi (cross-scan output) into scan bf16 buf 0
__global__ __launch_bounds__(128) void k_split_hi()
{
    int r = blockIdx.x;
    int c = threadIdx.x << 2;
    float4 v = *(const float4*)&g_Hi[(size_t)r * HS + c];
    uint2 h, l;
    split4(v, h, l);
    *(uint2*)&g_Hbh0[(size_t)r * HS + c] = h;
    *(uint2*)&g_Hbl0[(size_t)r * HS + c] = l;
}

// ---------------- bf16x3 big GEMM via mma.sync (proven 220us config) ----------------
#define GEMM_SMEM (4 * 128 * 72 * 2)     // 73728 bytes

__global__ __launch_bounds__(256) void k_gemm_mma(float* __restrict__ Out, int mode, int wsel)
{
    if (mode == 1) Out = g_bxc;
    const __nv_bfloat16* Wh = wsel ? g_Chi : g_Whi;
    const __nv_bfloat16* Wl = wsel ? g_Clo : g_Wlo;

    extern __shared__ __nv_bfloat16 sb[];
    __nv_bfloat16* sAh = sb;
    __nv_bfloat16* sAl = sb + 9216;
    __nv_bfloat16* sWh = sb + 18432;
    __nv_bfloat16* sWl = sb + 27648;

    const int tid  = threadIdx.x;
    const int lane = tid & 31;
    const int wid  = tid >> 5;
    const int row0 = blockIdx.y << 7;
    const int col0 = blockIdx.x << 7;
    const int wm   = wid >> 2;
    const int wn   = wid & 3;

    const int lrow = tid >> 1;
    const int lseg = (tid & 1) << 5;

    float acc[4][4][4];
#pragma unroll
    for (int mt = 0; mt < 4; ++mt)
#pragma unroll
        for (int nt = 0; nt < 4; ++nt)
#pragma unroll
            for (int q = 0; q < 4; ++q) acc[mt][nt][q] = 0.f;

    const uint32_t sAh32 = smem_u32(sAh);
    const uint32_t sAl32 = smem_u32(sAl);
    const uint32_t sWh32 = smem_u32(sWh);
    const uint32_t sWl32 = smem_u32(sWl);

    const uint32_t a_lrow = (uint32_t)(wm * 64 + (lane & 15));
    const uint32_t b_lrow = (uint32_t)(wn * 32 + (lane & 15));
    const uint32_t khalf  = (uint32_t)((lane >> 4) << 3);

    for (int kc = 0; kc < 8; ++kc) {
        __syncthreads();
        {
            const size_t gA = (size_t)(row0 + lrow) * HS + kc * 64 + lseg;
            const size_t gW = (size_t)(col0 + lrow) * HS + kc * 64 + lseg;
            const uint32_t so = (uint32_t)(lrow * 72 + lseg);
#pragma unroll
            for (int i = 0; i < 4; ++i) {
                *(uint4*)(sAh + so + i*8) = *(const uint4*)(g_Ahi + gA + i*8);
                *(uint4*)(sAl + so + i*8) = *(const uint4*)(g_Alo + gA + i*8);
                *(uint4*)(sWh + so + i*8) = *(const uint4*)(Wh + gW + i*8);
                *(uint4*)(sWl + so + i*8) = *(const uint4*)(Wl + gW + i*8);
            }
        }
        __syncthreads();

#pragma unroll
        for (int ks = 0; ks < 4; ++ks) {
            const uint32_t kcol = (uint32_t)(ks * 16) + khalf;
            uint32_t ah[4][4], al[4][4], bh[4][2], bl[4][2];
#pragma unroll
            for (int mt = 0; mt < 4; ++mt) {
                uint32_t off = ((a_lrow + mt*16) * 72 + kcol) * 2;
                ldmx4(ah[mt], sAh32 + off);
                ldmx4(al[mt], sAl32 + off);
            }
#pragma unroll
            for (int bt = 0; bt < 2; ++bt) {
                uint32_t off = ((b_lrow + bt*16) * 72 + kcol) * 2;
                uint32_t qh[4], ql[4];
                ldmx4(qh, sWh32 + off);
                ldmx4(ql, sWl32 + off);
                bh[2*bt+0][0] = qh[0]; bh[2*bt+0][1] = qh[2];
                bh[2*bt+1][0] = qh[1]; bh[2*bt+1][1] = qh[3];
                bl[2*bt+0][0] = ql[0]; bl[2*bt+0][1] = ql[2];
                bl[2*bt+1][0] = ql[1]; bl[2*bt+1][1] = ql[3];
            }
#pragma unroll
            for (int mt = 0; mt < 4; ++mt)
#pragma unroll
                for (int nt = 0; nt < 4; ++nt) {
                    mma16816(acc[mt][nt], ah[mt], bh[nt]);
                    mma16816(acc[mt][nt], ah[mt], bl[nt]);
                    mma16816(acc[mt][nt], al[mt], bh[nt]);
                }
        }
    }

    const int r_base = row0 + wm * 64 + (lane >> 2);
    const int c_base = col0 + wn * 32 + ((lane & 3) << 1);
#pragma unroll
    for (int mt = 0; mt < 4; ++mt)
#pragma unroll
        for (int nt = 0; nt < 4; ++nt) {
            size_t o0 = (size_t)(r_base + mt*16)     * HS + c_base + nt*8;
            size_t o1 = (size_t)(r_base + mt*16 + 8) * HS + c_base + nt*8;
            *(float2*)&Out[o0] = make_float2(acc[mt][nt][0], acc[mt][nt][1]);
            *(float2*)&Out[o1] = make_float2(acc[mt][nt][2], acc[mt][nt][3]);
        }
}

// ---------------- persistent tensor-core scan + cp.async H double buffer ----------------
// smem halves: sAh [8][64][72] @0, sAl @36864,
//              H bufs: b in {0,1} at 73728 + b*9216 (hi @+0, lo @+4608)
#define SCANT_SMEM ((8*64*72*2 + 2*64*72*2) * 2)   // 184320 bytes

__global__ __launch_bounds__(256) void k_scan_mma(int phase, float* __restrict__ hsp,
                                                  int hsmode, const float* __restrict__ Aw)
{
    extern __shared__ __nv_bfloat16 sx[];
    __nv_bfloat16* sAh = sx;                       // [8][64][72]
    __nv_bfloat16* sAl = sx + 36864;

    const int tid  = threadIdx.x;
    const int lane = tid & 31;
    const int wid  = tid >> 5;
    const int wm   = wid >> 2;          // 0..1
    const int wn   = wid & 3;           // 0..3
    const int col0 = blockIdx.x << 6;
    const int rb   = blockIdx.y;
    const int row0 = rb << 6;

    if (hsmode == 2) hsp = g_hs;

    // one-time: split A rows [col0, col0+64) into resident bf16 hi/lo
    for (int e = tid; e < 64 * 128; e += 256) {
        int row = e >> 7;
        int c4  = (e & 127) << 2;
        float4 v = *(const float4*)&Aw[(size_t)(col0 + row) * HS + c4];
        uint2 h, l;
        split4(v, h, l);
        int off = ((c4 >> 6) * 4608) + row * 72 + (c4 & 63);
        *(uint2*)&sAh[off] = h;
        *(uint2*)&sAl[off] = l;
    }
    __syncthreads();

    const uint32_t s32 = smem_u32(sx);
    const uint32_t sAh32 = s32, sAl32 = s32 + 36864 * 2;

    const uint32_t a_lrow = (uint32_t)(wm * 32 + (lane & 15));
    const uint32_t b_lrow = (uint32_t)(wn * 16 + (lane & 15));
    const uint32_t khalf  = (uint32_t)((lane >> 4) << 3);
    const int srow = tid >> 2;           // stage row 0..63
    const int sseg = (tid & 3) << 4;     // stage seg 0/16/32/48 halves

    const unsigned base = phase ? (8u * LC) : 0u;
    unsigned* cnt = &g_cntA[rb];

    for (int i = 0; i < LC; ++i) {
        const __nv_bfloat16* Hh = (i & 1) ? g_Hbh1 : g_Hbh0;
        const __nv_bfloat16* Hl = (i & 1) ? g_Hbl1 : g_Hbl0;
        __nv_bfloat16* Oh = (i & 1) ? g_Hbh0 : g_Hbh1;
        __nv_bfloat16* Ol = (i & 1) ? g_Hbl0 : g_Hbl1;
        const float* bxs = g_bxc + (size_t)i * MR * HS;

        float acc[2][2][4];
#pragma unroll
        for (int mt = 0; mt < 2; ++mt)
#pragma unroll
            for (int nt = 0; nt < 2; ++nt)
#pragma unroll
                for (int q = 0; q < 4; ++q) acc[mt][nt][q] = 0.f;

        const bool skip = (phase == 0) && (i == 0);   // H input is all zeros
        if (!skip) {
            auto stageH = [&](int kc, int b) {
                size_t g = (size_t)(row0 + srow) * HS + kc * 64 + sseg;
                uint32_t d = s32 + (uint32_t)(73728 + b * 9216 + srow * 72 + sseg) * 2;
                cp16(d,      Hh + g);
                cp16(d + 16, Hh + g + 8);
                cp16(d + 4608 * 2,      Hl + g);
                cp16(d + 4608 * 2 + 16, Hl + g + 8);
            };

            stageH(0, 0); CP_COMMIT();

            for (int kc = 0; kc < 8; ++kc) {
                const int b = kc & 1;
                if (kc < 7) { stageH(kc + 1, b ^ 1); CP_COMMIT(); CP_WAIT(1); }
                else        { CP_WAIT(0); }
                __syncthreads();

                const uint32_t hbase = (uint32_t)(73728 + b * 9216);
                const uint32_t bbase = (uint32_t)(kc * 4608);
#pragma unroll
                for (int ks = 0; ks < 4; ++ks) {
                    const uint32_t kcol = (uint32_t)(ks * 16) + khalf;
                    uint32_t ah[2][4], al[2][4];
#pragma unroll
                    for (int mt = 0; mt < 2; ++mt) {
                        uint32_t off = s32 + (hbase + (a_lrow + mt*16) * 72 + kcol) * 2;
                        ldmx4(ah[mt], off);
                        ldmx4(al[mt], off + 4608 * 2);
                    }
                    uint32_t qh[4], ql[4];
                    {
                        uint32_t off = (bbase + b_lrow * 72 + kcol) * 2;
                        ldmx4(qh, sAh32 + off);
                        ldmx4(ql, sAl32 + off);
                    }
                    uint32_t bh[2][2] = {{qh[0], qh[2]}, {qh[1], qh[3]}};
                    uint32_t bl[2][2] = {{ql[0], ql[2]}, {ql[1], ql[3]}};
#pragma unroll
                    for (int mt = 0; mt < 2; ++mt)
#pragma unroll
                        for (int nt = 0; nt < 2; ++nt) {
                            mma16816(acc[mt][nt], ah[mt], bh[nt]);
                            mma16816(acc[mt][nt], ah[mt], bl[nt]);
                            mma16816(acc[mt][nt], al[mt], bh[nt]);
                        }
                }
                __syncthreads();   // protect buf b from next iteration's cp.async
            }
        }

        // epilogue: add bx; write bf16 pair; fp32 finals only where consumed
        const int r_b = row0 + wm * 32 + (lane >> 2);
        const int c_b = col0 + wn * 16 + ((lane & 3) << 1);
        const bool wr_final = (phase == 0) && (i == LC - 1);
#pragma unroll
        for (int mt = 0; mt < 2; ++mt)
#pragma unroll
            for (int nt = 0; nt < 2; ++nt) {
                int r0 = r_b + mt * 16;
                int c  = c_b + nt * 8;
                size_t o0 = (size_t)r0 * HS + c;
                size_t o1 = (size_t)(r0 + 8) * HS + c;
                float2 b0 = *(const float2*)&bxs[o0];
                float2 b1 = *(const float2*)&bxs[o1];
                float v00 = acc[mt][nt][0] + b0.x, v01 = acc[mt][nt][1] + b0.y;
                float v10 = acc[mt][nt][2] + b1.x, v11 = acc[mt][nt][3] + b1.y;
                uint32_t h0, l0, h1, l1;
                split2(v00, v01, h0, l0);
                split2(v10, v11, h1, l1);
                *(uint32_t*)&Oh[o0] = h0;  *(uint32_t*)&Ol[o0] = l0;
                *(uint32_t*)&Oh[o1] = h1;  *(uint32_t*)&Ol[o1] = l1;
                if (wr_final) {
                    *(float2*)&g_H0[o0] = make_float2(v00, v01);
                    *(float2*)&g_H0[o1] = make_float2(v10, v11);
                }
                if (hsmode) {
                    size_t ho0 = ((size_t)(r0 & 15) * SS + ((r0 >> 4) << 5) + i) * HS + c;
                    int r1 = r0 + 8;
                    size_t ho1 = ((size_t)(r1 & 15) * SS + ((r1 >> 4) << 5) + i) * HS + c;
                    *(float2*)&hsp[ho0] = make_float2(v00, v01);
                    *(float2*)&hsp[ho1] = make_float2(v10, v11);
                    *(uint32_t*)&g_Ahi[ho0] = h0;  *(uint32_t*)&g_Alo[ho0] = l0;
                    *(uint32_t*)&g_Ahi[ho1] = h1;  *(uint32_t*)&g_Alo[ho1] = l1;
                }
            }
        gbar(cnt, base + 8u * (i + 1));
    }
}

// ---------------- fused squarings: A^32 via 5 squarings, one launch ----------------
__global__ __launch_bounds__(128) void k_sq_fused(const float* __restrict__ A0)
{
    __shared__ float sI[16][68];
    __shared__ float sW[16][68];

    const int tid  = threadIdx.x;
    const int row0 = (blockIdx.x >> 3) << 6;
    const int col0 = (blockIdx.x & 7) << 6;
    const int lr   = tid >> 1;
    const int lk   = (tid & 1) << 3;
    const int kk2  = tid >> 4;
    const int nq   = (tid & 15) << 2;
    const int tx = tid & 7, ty = tid >> 3;

    for (int s = 0; s < 5; ++s) {
        const float* X;
        float* Outp;
        if (s == 0)      { X = A0;   Outp = g_P0; }
        else if (s & 1)  { X = g_P0; Outp = g_P1; }
        else             { X = g_P1; Outp = g_P0; }

        const float* ip = X + (size_t)(row0 + lr) * HS + lk;

        float acc[4][8];
#pragma unroll
        for (int i = 0; i < 4; i++)
#pragma unroll
            for (int j = 0; j < 8; j++) acc[i][j] = 0.f;

        for (int k0 = 0; k0 < HS; k0 += 16) {
            float4 a0 = *(const float4*)(ip + k0);
            float4 a1 = *(const float4*)(ip + k0 + 4);
            float4 y0 = *(const float4*)&X[(size_t)(k0 + kk2)     * HS + col0 + nq];
            float4 y1 = *(const float4*)&X[(size_t)(k0 + kk2 + 8) * HS + col0 + nq];
            sI[lk+0][lr]=a0.x; sI[lk+1][lr]=a0.y; sI[lk+2][lr]=a0.z; sI[lk+3][lr]=a0.w;
            sI[lk+4][lr]=a1.x; sI[lk+5][lr]=a1.y; sI[lk+6][lr]=a1.z; sI[lk+7][lr]=a1.w;
            *(float4*)&sW[kk2][nq]     = y0;
            *(float4*)&sW[kk2 + 8][nq] = y1;
            __syncthreads();
#pragma unroll
            for (int k = 0; k < 16; k++) {
                float4 ri = *(const float4*)&sI[k][ty << 2];
                float4 w0 = *(const float4*)&sW[k][tx << 3];
                float4 w1 = *(const float4*)&sW[k][(tx << 3) + 4];
                float rr[4] = {ri.x, ri.y, ri.z, ri.w};
                float ww[8] = {w0.x, w0.y, w0.z, w0.w, w1.x, w1.y, w1.z, w1.w};
#pragma unroll
                for (int i = 0; i < 4; i++)
#pragma unroll
                    for (int j = 0; j < 8; j++) acc[i][j] += rr[i] * ww[j];
            }
            __syncthreads();
        }
#pragma unroll
        for (int i = 0; i < 4; i++) {
            size_t o = (size_t)(row0 + (ty << 2) + i) * HS + col0 + (tx << 3);
            *(float4*)&Outp[o]     = make_float4(acc[i][0], acc[i][1], acc[i][2], acc[i][3]);
            *(float4*)&Outp[o + 4] = make_float4(acc[i][4], acc[i][5], acc[i][6], acc[i][7]);
        }
        gbar(&g_cntS, 64u * (unsigned)(s + 1));
    }
}

// ---------------- persistent cross-chunk scan ----------------
__global__ __launch_bounds__(256) void k_cross_persist()
{
    __shared__ float sS[16][516];
    const float* AL = g_P0;              // A^32
    const int t  = threadIdx.x;
    const int n0 = blockIdx.x << 4;
    const int r  = t & 15;
    const int no = t >> 4;
    const int n  = n0 + no;
    const float* arow = AL + (size_t)n * HS;

    for (int j = 1; j < CC; ++j) {
        const float* sprev = g_Hi + (size_t)(j - 1) * BS * HS;
        const float* fprev = g_H0 + (size_t)(j - 1) * BS * HS;
        float*       sout  = g_Hi + (size_t)j * BS * HS;

        for (int e = t; e < BS * HS / 4; e += 256) {
            float4 v = ((const float4*)sprev)[e];
            int rr = e >> 7;
            int kk = (e & 127) << 2;
            *(float4*)&sS[rr][kk] = v;
        }
        __syncthreads();

        float a0 = 0.f, a1 = 0.f, a2 = 0.f, a3 = 0.f;
#pragma unroll 4
        for (int k = 0; k < HS; k += 16) {
            float4 v0 = *(const float4*)&arow[k];
            float4 v1 = *(const float4*)&arow[k + 4];
            float4 v2 = *(const float4*)&arow[k + 8];
            float4 v3 = *(const float4*)&arow[k + 12];
            a0 += v0.x*sS[r][k+0]  + v0.y*sS[r][k+1]  + v0.z*sS[r][k+2]  + v0.w*sS[r][k+3];
            a1 += v1.x*sS[r][k+4]  + v1.y*sS[r][k+5]  + v1.z*sS[r][k+6]  + v1.w*sS[r][k+7];
            a2 += v2.x*sS[r][k+8]  + v2.y*sS[r][k+9]  + v2.z*sS[r][k+10] + v2.w*sS[r][k+11];
            a3 += v3.x*sS[r][k+12] + v3.y*sS[r][k+13] + v3.z*sS[r][k+14] + v3.w*sS[r][k+15];
        }
        sout[(size_t)r * HS + n] = (a0 + a1) + (a2 + a3) + fprev[(size_t)r * HS + n];
        gbar(&g_cnt3, 32u * (unsigned)j);
    }
}

// ---------------- launch ----------------
extern "C" void kernel_launch(void* const* d_in, const int* in_sizes, int n_in,
                              void* d_out, int out_size)
{
    const float* x  = (const float*)d_in[0];
    const float* Aw = (const float*)d_in[1];
    const float* Bw = (const float*)d_in[2];
    const float* Cw = (const float*)d_in[3];
    float* out = (float*)d_out;

    const size_t YS = (size_t)BS * SS * HS;
    bool both = (size_t)out_size >= 2 * YS;     // output = (ys, hs) concatenated
    float* hsp = both ? out + YS : nullptr;
    int hsmode = both ? 1 : 2;

    cudaFuncSetAttribute(k_scan_mma,
                         cudaFuncAttributeMaxDynamicSharedMemorySize, SCANT_SMEM);
    cudaFuncSetAttribute(k_gemm_mma,
                         cudaFuncAttributeMaxDynamicSharedMemorySize, GEMM_SMEM);

    // 0) fused: zero buffers + split x/B/C
    k_init<<<34816, 128>>>(x, Bw, Cw);

    // 1) bx = x @ B^T via mma.sync bf16x3 -> g_bxc
    k_gemm_mma<<<dim3(4, 256), 256, GEMM_SMEM>>>(nullptr, 1, 0);

    // 2) A^32 by fused repeated squaring
    k_sq_fused<<<64, 128>>>(Aw);

    // 3) phase 1: tensor-core local scans (zero init)  [ncu profiles this launch]
    k_scan_mma<<<dim3(8, 16), 256, SCANT_SMEM>>>(0, nullptr, 0, Aw);

    // 4) phase 2: cross-chunk scan, persistent
    k_cross_persist<<<32, 256>>>();

    // 5) seed phase-3 initial states (bf16 split of g_Hi)
    k_split_hi<<<MR, 128>>>();

    // 6) phase 3: tensor-core local scans, writes hs + ys-GEMM operands
    k_scan_mma<<<dim3(8, 16), 256, SCANT_SMEM>>>(1, hsp, hsmode, Aw);

    // 7) ys = hs @ C^T via mma.sync bf16x3 (C split done in k_init)
    k_gemm_mma<<<dim3(4, 256), 256, GEMM_SMEM>>>(out, 0, 1);
}